// round 1
// baseline (speedup 1.0000x reference)
#include <cuda_runtime.h>

#define DIMV 128
#define NA 16
#define NMOL 64
#define NTOT 1024
#define EPSV 1e-12f

// per-molecule scratch (allocation-free: __device__ globals)
__device__ float g_Wm[NMOL * DIMV];
__device__ float g_Mm[NMOL * DIMV];
__device__ float g_bil[NMOL * DIMV];

// dynamic smem layout (floats)
#define OFF_E    0                  // Etile: 256 rows x 128 = 32768
#define OFF_M    (OFF_E + 32768)    // mps0 -> mps : 16x128
#define OFF_C    (OFF_M + 2048)     // contri -> w : 16x128
#define OFF_RED  (OFF_C + 2048)     // 4x128 reduction scratch
#define OFF_ADJ  (OFF_RED + 512)    // 16x16 adjacency block
#define OFF_NORM (OFF_ADJ + 256)    // 16 inverse norms (padded)
#define OFF_IDX  (OFF_NORM + 32)    // 256 ints (fp idx, then bond idx)
#define SMEM_FLOATS (OFF_IDX + 256)

extern __shared__ float smem[];

__global__ __launch_bounds__(512, 1) void k_mol(
    const int* __restrict__ fp, const float* __restrict__ adj,
    const int* __restrict__ bidx, const float* __restrict__ E_fp,
    const float* __restrict__ E_bond, const float* __restrict__ W_fp,
    const float* __restrict__ b_fp)
{
    float* sE = smem + OFF_E;
    float* sM = smem + OFF_M;
    float* sC = smem + OFF_C;
    float* sRed = smem + OFF_RED;
    float* sAdj = smem + OFF_ADJ;
    float* sNorm = smem + OFF_NORM;
    int* sIdx = (int*)(smem + OFF_IDX);

    const int tid = threadIdx.x;
    const int m = blockIdx.x;
    const int base = m * NA;
    const int c = tid & 127;
    const int g = tid >> 7;      // 0..3, each group handles 4 atom rows
    const int r0 = 4 * g;

    // fingerprint indices + adjacency block
    if (tid < NA) sIdx[tid] = fp[base + tid];
    for (int i = tid; i < NA * NA; i += 512) {
        int r = i >> 4, b = i & 15;
        sAdj[i] = adj[(base + r) * NTOT + base + b];
    }
    __syncthreads();

    // mps0 = E_fp[fp]
    for (int i = tid; i < NA * DIMV; i += 512) {
        int r = i >> 7, cc = i & 127;
        sM[i] = E_fp[sIdx[r] * DIMV + cc];
    }
    __syncthreads();

    // contri = relu(mps0 @ W_fp + b_fp)
    {
        float bv = b_fp[c];
        float a0 = bv, a1 = bv, a2 = bv, a3 = bv;
        #pragma unroll 4
        for (int k = 0; k < DIMV; k++) {
            float wv = W_fp[k * DIMV + c];
            a0 += sM[(r0 + 0) * DIMV + k] * wv;
            a1 += sM[(r0 + 1) * DIMV + k] * wv;
            a2 += sM[(r0 + 2) * DIMV + k] * wv;
            a3 += sM[(r0 + 3) * DIMV + k] * wv;
        }
        sC[(r0 + 0) * DIMV + c] = fmaxf(a0, 0.f);
        sC[(r0 + 1) * DIMV + c] = fmaxf(a1, 0.f);
        sC[(r0 + 2) * DIMV + c] = fmaxf(a2, 0.f);
        sC[(r0 + 3) * DIMV + c] = fmaxf(a3, 0.f);
    }
    __syncthreads();

    // mps = mps0 + adj_block @ contri   (in place on sM)
    {
        #pragma unroll
        for (int j = 0; j < 4; j++) {
            int r = r0 + j;
            float v = sM[r * DIMV + c];
            #pragma unroll
            for (int b = 0; b < NA; b++)
                v += sAdj[r * NA + b] * sC[b * DIMV + c];
            sM[r * DIMV + c] = v;
        }
    }
    __syncthreads();

    // per-row L2 norms (16 warps, warp w -> row w)
    {
        int w = tid >> 5, l = tid & 31;
        float v0 = sM[w * DIMV + l], v1 = sM[w * DIMV + l + 32];
        float v2 = sM[w * DIMV + l + 64], v3 = sM[w * DIMV + l + 96];
        float s = v0 * v0 + v1 * v1 + v2 * v2 + v3 * v3;
        #pragma unroll
        for (int o = 16; o > 0; o >>= 1) s += __shfl_xor_sync(0xffffffffu, s, o);
        if (l == 0) sNorm[w] = 1.0f / fmaxf(sqrtf(s), EPSV);
    }
    __syncthreads();
    {
        #pragma unroll
        for (int j = 0; j < 4; j++)
            sM[(r0 + j) * DIMV + c] *= sNorm[r0 + j];
    }
    __syncthreads();

    // in-block bond indices
    for (int i = tid; i < NA * NA; i += 512) {
        int a = i >> 4, b = i & 15;
        sIdx[i] = bidx[(base + a) * NTOT + base + b];
    }
    __syncthreads();

    // gather E_bond tile: 256 rows x 128
    for (int i = tid; i < NA * NA * DIMV; i += 512) {
        int row = i >> 7, cc = i & 127;
        sE[i] = E_bond[sIdx[row] * DIMV + cc];
    }
    __syncthreads();

    float e0c = E_bond[c];   // E_bond row 0 (off-block fill)

    // s[a,c] over full b axis; w = mps / max(sqrt(s), eps)
    {
        #pragma unroll
        for (int j = 0; j < 4; j++) {
            int a = r0 + j;
            float s = (float)(NTOT - NA) * e0c * e0c;
            #pragma unroll
            for (int b = 0; b < NA; b++) {
                float e = sE[(a * NA + b) * DIMV + c];
                s += e * e;
            }
            float inv = 1.0f / fmaxf(sqrtf(s), EPSV);
            sC[a * DIMV + c] = sM[a * DIMV + c] * inv;   // w
        }
    }
    __syncthreads();

    // bil[c] = sum_{a,b} w[a,c] * mps[b,c] * E[a,b,c]   (partials per group)
    {
        float bilp = 0.f;
        #pragma unroll
        for (int j = 0; j < 4; j++) {
            int a = r0 + j;
            float pa = 0.f;
            #pragma unroll
            for (int b = 0; b < NA; b++)
                pa += sM[b * DIMV + c] * sE[(a * NA + b) * DIMV + c];
            bilp += sC[a * DIMV + c] * pa;
        }
        sRed[g * DIMV + c] = bilp;
    }
    __syncthreads();

    if (g == 0) {
        float bil = sRed[c] + sRed[DIMV + c] + sRed[2 * DIMV + c] + sRed[3 * DIMV + c];
        float wm = 0.f, mm = 0.f;
        #pragma unroll
        for (int a = 0; a < NA; a++) {
            wm += sC[a * DIMV + c];
            mm += sM[a * DIMV + c];
        }
        g_bil[m * DIMV + c] = bil;
        g_Wm[m * DIMV + c] = wm;
        g_Mm[m * DIMV + c] = mm;
    }
}

__global__ __launch_bounds__(128, 1) void k_out(
    const float* __restrict__ E_bond,
    const float* __restrict__ W0, const float* __restrict__ b0,
    const float* __restrict__ W1, const float* __restrict__ b1,
    const float* __restrict__ Wp, const float* __restrict__ bp,
    float* __restrict__ out)
{
    __shared__ float sx[DIMV];
    __shared__ float sy[DIMV];
    __shared__ float sr[4];
    const int c = threadIdx.x;
    const int m = blockIdx.x;

    // S[c] = sum over all molecules of Wm (redundant per block; 64 coalesced loads)
    float S = 0.f;
    #pragma unroll 8
    for (int mm = 0; mm < NMOL; mm++) S += g_Wm[mm * DIMV + c];

    float e0c = E_bond[c];
    float tn = g_bil[m * DIMV + c] + e0c * (S - g_Wm[m * DIMV + c]) * g_Mm[m * DIMV + c];
    sx[c] = tn;
    __syncthreads();

    float a0 = b0[c];
    #pragma unroll 4
    for (int k = 0; k < DIMV; k++) a0 += sx[k] * W0[k * DIMV + c];
    sy[c] = fmaxf(a0, 0.f);
    __syncthreads();

    float a1 = b1[c];
    #pragma unroll 4
    for (int k = 0; k < DIMV; k++) a1 += sy[k] * W1[k * DIMV + c];
    a1 = fmaxf(a1, 0.f);

    float r = a1 * Wp[c];
    #pragma unroll
    for (int o = 16; o > 0; o >>= 1) r += __shfl_xor_sync(0xffffffffu, r, o);
    if ((c & 31) == 0) sr[c >> 5] = r;
    __syncthreads();
    if (c == 0) out[m] = sr[0] + sr[1] + sr[2] + sr[3] + bp[0];
}

extern "C" void kernel_launch(void* const* d_in, const int* in_sizes, int n_in,
                              void* d_out, int out_size) {
    const int*   fp     = (const int*)d_in[0];
    const float* adj    = (const float*)d_in[1];
    const int*   bidx   = (const int*)d_in[2];
    const float* E_fp   = (const float*)d_in[3];
    const float* E_bond = (const float*)d_in[4];
    const float* W_fp   = (const float*)d_in[5];
    const float* b_fp   = (const float*)d_in[6];
    const float* W0     = (const float*)d_in[7];
    const float* b0     = (const float*)d_in[8];
    const float* W1     = (const float*)d_in[9];
    const float* b1     = (const float*)d_in[10];
    const float* Wp     = (const float*)d_in[11];
    const float* bp     = (const float*)d_in[12];
    float* out = (float*)d_out;

    size_t smem_bytes = SMEM_FLOATS * sizeof(float);
    cudaFuncSetAttribute(k_mol, cudaFuncAttributeMaxDynamicSharedMemorySize,
                         (int)smem_bytes);
    k_mol<<<NMOL, 512, smem_bytes>>>(fp, adj, bidx, E_fp, E_bond, W_fp, b_fp);
    k_out<<<NMOL, 128>>>(E_bond, W0, b0, W1, b1, Wp, bp, out);
}

// round 2
// speedup vs baseline: 1.9623x; 1.9623x over previous
#include <cuda_runtime.h>

#define DIMV 128
#define NA 16
#define NMOL 64
#define NTOT 1024
#define EPSV 1e-12f

// per-molecule scratch (allocation-free: __device__ globals)
__device__ float g_Wm[NMOL * DIMV];
__device__ float g_Mm[NMOL * DIMV];
__device__ float g_bil[NMOL * DIMV];

// dynamic smem layout (floats)
#define OFF_E    0                  // Etile: 256 rows x 128 = 32768
#define OFF_M    (OFF_E + 32768)    // mps0 -> mps : 16x128
#define OFF_C    (OFF_M + 2048)     // contri -> w : 16x128
#define OFF_RED  (OFF_C + 2048)     // 4x128 reduction scratch
#define OFF_ADJ  (OFF_RED + 512)    // 16x16 adjacency block
#define OFF_NORM (OFF_ADJ + 256)    // 16 inverse norms (padded)
#define OFF_IDX  (OFF_NORM + 32)    // 256 ints (fp idx, then bond idx)
#define SMEM_FLOATS (OFF_IDX + 256)

extern __shared__ float smem[];

__global__ __launch_bounds__(512, 1) void k_mol(
    const int* __restrict__ fp, const float* __restrict__ adj,
    const int* __restrict__ bidx, const float* __restrict__ E_fp,
    const float* __restrict__ E_bond, const float* __restrict__ W_fp,
    const float* __restrict__ b_fp)
{
    float* sE = smem + OFF_E;
    float* sM = smem + OFF_M;
    float* sC = smem + OFF_C;
    float* sRed = smem + OFF_RED;
    float* sAdj = smem + OFF_ADJ;
    float* sNorm = smem + OFF_NORM;
    int* sIdx = (int*)(smem + OFF_IDX);

    const int tid = threadIdx.x;
    const int m = blockIdx.x;
    const int base = m * NA;
    const int c = tid & 127;
    const int g = tid >> 7;      // 0..3, each group handles 4 atom rows
    const int r0 = 4 * g;

    // fingerprint indices + adjacency block
    if (tid < NA) sIdx[tid] = fp[base + tid];
    for (int i = tid; i < NA * NA; i += 512) {
        int r = i >> 4, b = i & 15;
        sAdj[i] = adj[(base + r) * NTOT + base + b];
    }
    __syncthreads();

    // mps0 = E_fp[fp]  (vectorized float4: 16 rows x 32 float4)
    {
        const float4* Ef4 = (const float4*)E_fp;
        float4* sM4 = (float4*)sM;
        int i = tid;                    // 512 elements, 1 per thread
        int r = i >> 5, cc = i & 31;
        sM4[i] = Ef4[sIdx[r] * (DIMV / 4) + cc];
    }
    __syncthreads();

    // contri = relu(mps0 @ W_fp + b_fp)
    {
        float bv = b_fp[c];
        float a0 = bv, a1 = bv, a2 = bv, a3 = bv;
        #pragma unroll 4
        for (int k = 0; k < DIMV; k++) {
            float wv = W_fp[k * DIMV + c];
            a0 += sM[(r0 + 0) * DIMV + k] * wv;
            a1 += sM[(r0 + 1) * DIMV + k] * wv;
            a2 += sM[(r0 + 2) * DIMV + k] * wv;
            a3 += sM[(r0 + 3) * DIMV + k] * wv;
        }
        sC[(r0 + 0) * DIMV + c] = fmaxf(a0, 0.f);
        sC[(r0 + 1) * DIMV + c] = fmaxf(a1, 0.f);
        sC[(r0 + 2) * DIMV + c] = fmaxf(a2, 0.f);
        sC[(r0 + 3) * DIMV + c] = fmaxf(a3, 0.f);
    }
    __syncthreads();

    // mps = mps0 + adj_block @ contri   (in place on sM)
    {
        #pragma unroll
        for (int j = 0; j < 4; j++) {
            int r = r0 + j;
            float v = sM[r * DIMV + c];
            #pragma unroll
            for (int b = 0; b < NA; b++)
                v += sAdj[r * NA + b] * sC[b * DIMV + c];
            sM[r * DIMV + c] = v;
        }
    }
    __syncthreads();

    // per-row L2 norms (16 warps, warp w -> row w)
    {
        int w = tid >> 5, l = tid & 31;
        float v0 = sM[w * DIMV + l], v1 = sM[w * DIMV + l + 32];
        float v2 = sM[w * DIMV + l + 64], v3 = sM[w * DIMV + l + 96];
        float s = v0 * v0 + v1 * v1 + v2 * v2 + v3 * v3;
        #pragma unroll
        for (int o = 16; o > 0; o >>= 1) s += __shfl_xor_sync(0xffffffffu, s, o);
        if (l == 0) sNorm[w] = 1.0f / fmaxf(sqrtf(s), EPSV);
    }
    __syncthreads();
    {
        #pragma unroll
        for (int j = 0; j < 4; j++)
            sM[(r0 + j) * DIMV + c] *= sNorm[r0 + j];
    }
    __syncthreads();

    // in-block bond indices
    for (int i = tid; i < NA * NA; i += 512) {
        int a = i >> 4, b = i & 15;
        sIdx[i] = bidx[(base + a) * NTOT + base + b];
    }
    __syncthreads();

    // gather E_bond tile: 256 rows x 128  (vectorized float4: 256 x 32)
    {
        const float4* Eb4 = (const float4*)E_bond;
        float4* sE4 = (float4*)sE;
        #pragma unroll
        for (int i = tid; i < NA * NA * (DIMV / 4); i += 512) {
            int row = i >> 5, cc = i & 31;
            sE4[i] = Eb4[sIdx[row] * (DIMV / 4) + cc];
        }
    }
    __syncthreads();

    float e0c = E_bond[c];   // E_bond row 0 (off-block fill)

    // s[a,c] over full b axis; w = mps / max(sqrt(s), eps)
    {
        #pragma unroll
        for (int j = 0; j < 4; j++) {
            int a = r0 + j;
            float s = (float)(NTOT - NA) * e0c * e0c;
            #pragma unroll
            for (int b = 0; b < NA; b++) {
                float e = sE[(a * NA + b) * DIMV + c];
                s += e * e;
            }
            float inv = 1.0f / fmaxf(sqrtf(s), EPSV);
            sC[a * DIMV + c] = sM[a * DIMV + c] * inv;   // w
        }
    }
    __syncthreads();

    // bil[c] = sum_{a,b} w[a,c] * mps[b,c] * E[a,b,c]   (partials per group)
    {
        float bilp = 0.f;
        #pragma unroll
        for (int j = 0; j < 4; j++) {
            int a = r0 + j;
            float pa = 0.f;
            #pragma unroll
            for (int b = 0; b < NA; b++)
                pa += sM[b * DIMV + c] * sE[(a * NA + b) * DIMV + c];
            bilp += sC[a * DIMV + c] * pa;
        }
        sRed[g * DIMV + c] = bilp;
    }
    __syncthreads();

    if (g == 0) {
        float bil = sRed[c] + sRed[DIMV + c] + sRed[2 * DIMV + c] + sRed[3 * DIMV + c];
        float wm = 0.f, mm = 0.f;
        #pragma unroll
        for (int a = 0; a < NA; a++) {
            wm += sC[a * DIMV + c];
            mm += sM[a * DIMV + c];
        }
        g_bil[m * DIMV + c] = bil;
        g_Wm[m * DIMV + c] = wm;
        g_Mm[m * DIMV + c] = mm;
    }
}

// k_out v2: 512 threads, k-dimension split 4 ways per output channel.
// thread (c, q): c = tid & 127 output channel, q = tid >> 7 k-slice.
__global__ __launch_bounds__(512, 1) void k_out(
    const float* __restrict__ E_bond,
    const float* __restrict__ W0, const float* __restrict__ b0,
    const float* __restrict__ W1, const float* __restrict__ b1,
    const float* __restrict__ Wp, const float* __restrict__ bp,
    float* __restrict__ out)
{
    __shared__ float sPart[4 * DIMV];
    __shared__ float sx[DIMV];
    __shared__ float sy[DIMV];
    __shared__ float sr[4];
    const int tid = threadIdx.x;
    const int c = tid & 127;
    const int q = tid >> 7;
    const int m = blockIdx.x;

    // S[c] = sum_m g_Wm[m,c], split 16 molecules per q-slice (independent loads)
    {
        float sp = 0.f;
        #pragma unroll
        for (int j = 0; j < 16; j++)
            sp += g_Wm[(q * 16 + j) * DIMV + c];
        sPart[q * DIMV + c] = sp;
    }
    __syncthreads();
    if (q == 0) {
        float S = sPart[c] + sPart[DIMV + c] + sPart[2 * DIMV + c] + sPart[3 * DIMV + c];
        float e0c = E_bond[c];
        sx[c] = g_bil[m * DIMV + c] + e0c * (S - g_Wm[m * DIMV + c]) * g_Mm[m * DIMV + c];
    }
    __syncthreads();

    // layer 0: 32 fully-unrolled independent loads per thread
    {
        float a = 0.f;
        #pragma unroll
        for (int j = 0; j < 32; j++) {
            int k = q * 32 + j;
            a += sx[k] * W0[k * DIMV + c];
        }
        sPart[q * DIMV + c] = a;
    }
    __syncthreads();
    if (q == 0)
        sy[c] = fmaxf(sPart[c] + sPart[DIMV + c] + sPart[2 * DIMV + c] + sPart[3 * DIMV + c] + b0[c], 0.f);
    __syncthreads();

    // layer 1
    {
        float a = 0.f;
        #pragma unroll
        for (int j = 0; j < 32; j++) {
            int k = q * 32 + j;
            a += sy[k] * W1[k * DIMV + c];
        }
        sPart[q * DIMV + c] = a;
    }
    __syncthreads();

    if (q == 0) {
        float a1 = fmaxf(sPart[c] + sPart[DIMV + c] + sPart[2 * DIMV + c] + sPart[3 * DIMV + c] + b1[c], 0.f);
        float r = a1 * Wp[c];
        #pragma unroll
        for (int o = 16; o > 0; o >>= 1) r += __shfl_xor_sync(0xffffffffu, r, o);
        if ((c & 31) == 0) sr[c >> 5] = r;
    }
    __syncthreads();
    if (tid == 0) out[m] = sr[0] + sr[1] + sr[2] + sr[3] + bp[0];
}

extern "C" void kernel_launch(void* const* d_in, const int* in_sizes, int n_in,
                              void* d_out, int out_size) {
    const int*   fp     = (const int*)d_in[0];
    const float* adj    = (const float*)d_in[1];
    const int*   bidx   = (const int*)d_in[2];
    const float* E_fp   = (const float*)d_in[3];
    const float* E_bond = (const float*)d_in[4];
    const float* W_fp   = (const float*)d_in[5];
    const float* b_fp   = (const float*)d_in[6];
    const float* W0     = (const float*)d_in[7];
    const float* b0     = (const float*)d_in[8];
    const float* W1     = (const float*)d_in[9];
    const float* b1     = (const float*)d_in[10];
    const float* Wp     = (const float*)d_in[11];
    const float* bp     = (const float*)d_in[12];
    float* out = (float*)d_out;

    size_t smem_bytes = SMEM_FLOATS * sizeof(float);
    cudaFuncSetAttribute(k_mol, cudaFuncAttributeMaxDynamicSharedMemorySize,
                         (int)smem_bytes);
    k_mol<<<NMOL, 512, smem_bytes>>>(fp, adj, bidx, E_fp, E_bond, W_fp, b_fp);
    k_out<<<NMOL, 512>>>(E_bond, W0, b0, W1, b1, Wp, bp, out);
}

// round 9
// speedup vs baseline: 2.8082x; 1.4310x over previous
#include <cuda_runtime.h>
#include <cstdint>

#define DIMV 128
#define NA 16
#define NMOL 64
#define NTOT 1024
#define EPSV 1e-12f

// per-molecule scratch (allocation-free: __device__ globals)
__device__ float g_Wm[NMOL * DIMV];
__device__ float g_Mm[NMOL * DIMV];
__device__ float g_bil[NMOL * DIMV];

// dynamic smem layout (floats)
#define OFF_E    0                    // E_bond tile: 256 x 128 = 32768
#define OFF_P    (OFF_E + 32768)      // GEMM partials: 4 x 16 x 128 = 8192
#define OFF_M    (OFF_P + 8192)       // mps0 -> mps : 16x128
#define OFF_C    (OFF_M + 2048)       // contri -> w : 16x128
#define OFF_RED  (OFF_C + 2048)       // 4x128 reduction scratch
#define OFF_ADJ  (OFF_RED + 512)      // 16x16 adjacency block
#define OFF_NORM (OFF_ADJ + 256)      // 16 inverse norms (padded)
#define OFF_IDX  (OFF_NORM + 32)      // 16 fp indices (padded to 32)
#define OFF_IDXB (OFF_IDX + 32)       // 256 bond indices
#define SMEM_FLOATS (OFF_IDXB + 256)

extern __shared__ float smem[];

__device__ __forceinline__ void cp_async16(unsigned int saddr, const void* gptr) {
    asm volatile("cp.async.cg.shared.global [%0], [%1], 16;\n"
                 :: "r"(saddr), "l"(gptr));
}

__global__ __launch_bounds__(512, 1) void k_mol(
    const int* __restrict__ fp, const float* __restrict__ adj,
    const int* __restrict__ bidx, const float* __restrict__ E_fp,
    const float* __restrict__ E_bond, const float* __restrict__ W_fp,
    const float* __restrict__ b_fp)
{
    float* sE = smem + OFF_E;
    float* sP = smem + OFF_P;
    float* sM = smem + OFF_M;
    float* sC = smem + OFF_C;
    float* sRed = smem + OFF_RED;
    float* sAdj = smem + OFF_ADJ;
    float* sNorm = smem + OFF_NORM;
    int* sIdx = (int*)(smem + OFF_IDX);
    int* sIdxB = (int*)(smem + OFF_IDXB);

    const int tid = threadIdx.x;
    const int m = blockIdx.x;
    const int base = m * NA;
    const int c = tid & 127;
    const int g = tid >> 7;      // 0..3
    const int r0 = 4 * g;

    // ---- stage 0: indices + adjacency (one batch of independent loads) ----
    if (tid < NA) sIdx[tid] = fp[base + tid];
    if (tid < NA * NA) {
        int a = tid >> 4, b = tid & 15;
        sIdxB[tid] = bidx[(base + a) * NTOT + base + b];
        sAdj[tid] = adj[(base + a) * NTOT + base + b];
    }
    // independent per-thread loads issued now, used later
    float bv = b_fp[c];
    float e0c = E_bond[c];
    // W_fp column slice into registers: k in [32g, 32g+32)
    float wreg[32];
    #pragma unroll
    for (int j = 0; j < 32; j++)
        wreg[j] = W_fp[(g * 32 + j) * DIMV + c];
    __syncthreads();

    // ---- stage 1: async E_bond gather (hidden behind GEMM) + E_fp gather ----
    {
        const float4* Eb4 = (const float4*)E_bond;
        unsigned int sE_base = (unsigned int)__cvta_generic_to_shared(sE);
        #pragma unroll
        for (int i = tid; i < NA * NA * (DIMV / 4); i += 512) {
            int row = i >> 5, cc = i & 31;
            cp_async16(sE_base + i * 16, &Eb4[sIdxB[row] * (DIMV / 4) + cc]);
        }
        asm volatile("cp.async.commit_group;\n");
    }
    {
        const float4* Ef4 = (const float4*)E_fp;
        float4* sM4 = (float4*)sM;
        int r = tid >> 5, cc = tid & 31;
        sM4[tid] = Ef4[sIdx[r] * (DIMV / 4) + cc];
    }
    __syncthreads();

    // ---- stage 2: contri GEMM partials, k-split 4 ways ----
    {
        #pragma unroll
        for (int r = 0; r < NA; r++) {
            const float4* row4 = (const float4*)(sM + r * DIMV + g * 32);
            float a = 0.f;
            #pragma unroll
            for (int jv = 0; jv < 8; jv++) {
                float4 mv = row4[jv];
                a += mv.x * wreg[jv * 4 + 0];
                a += mv.y * wreg[jv * 4 + 1];
                a += mv.z * wreg[jv * 4 + 2];
                a += mv.w * wreg[jv * 4 + 3];
            }
            sP[(g * NA + r) * DIMV + c] = a;
        }
    }
    __syncthreads();

    // reduce partials -> contri = relu(. + b)
    {
        #pragma unroll
        for (int j = 0; j < 4; j++) {
            int r = r0 + j;
            float v = bv + sP[r * DIMV + c] + sP[(NA + r) * DIMV + c]
                    + sP[(2 * NA + r) * DIMV + c] + sP[(3 * NA + r) * DIMV + c];
            sC[r * DIMV + c] = fmaxf(v, 0.f);
        }
    }
    __syncthreads();

    // ---- stage 3: mps = mps0 + adj_block @ contri (in place on sM) ----
    {
        #pragma unroll
        for (int j = 0; j < 4; j++) {
            int r = r0 + j;
            float v = sM[r * DIMV + c];
            #pragma unroll
            for (int b = 0; b < NA; b++)
                v += sAdj[r * NA + b] * sC[b * DIMV + c];
            sM[r * DIMV + c] = v;
        }
    }
    __syncthreads();

    // ---- stage 4: per-row L2 norms (16 warps, warp w -> row w) ----
    {
        int w = tid >> 5, l = tid & 31;
        float v0 = sM[w * DIMV + l], v1 = sM[w * DIMV + l + 32];
        float v2 = sM[w * DIMV + l + 64], v3 = sM[w * DIMV + l + 96];
        float s = v0 * v0 + v1 * v1 + v2 * v2 + v3 * v3;
        #pragma unroll
        for (int o = 16; o > 0; o >>= 1) s += __shfl_xor_sync(0xffffffffu, s, o);
        if (l == 0) sNorm[w] = 1.0f / fmaxf(sqrtf(s), EPSV);
    }
    __syncthreads();
    {
        #pragma unroll
        for (int j = 0; j < 4; j++)
            sM[(r0 + j) * DIMV + c] *= sNorm[r0 + j];
    }

    // ---- stage 5: wait for E_bond tile, then s / w / bil ----
    asm volatile("cp.async.wait_group 0;\n" ::: "memory");
    __syncthreads();

    // s[a,c] over full b axis; w = mps / max(sqrt(s), eps)
    {
        #pragma unroll
        for (int j = 0; j < 4; j++) {
            int a = r0 + j;
            float s = (float)(NTOT - NA) * e0c * e0c;
            #pragma unroll
            for (int b = 0; b < NA; b++) {
                float e = sE[(a * NA + b) * DIMV + c];
                s += e * e;
            }
            float inv = 1.0f / fmaxf(sqrtf(s), EPSV);
            sC[a * DIMV + c] = sM[a * DIMV + c] * inv;   // w
        }
    }
    __syncthreads();

    // bil[c] = sum_{a,b} w[a,c] * mps[b,c] * E[a,b,c]   (partials per group)
    {
        float bilp = 0.f;
        #pragma unroll
        for (int j = 0; j < 4; j++) {
            int a = r0 + j;
            float pa = 0.f;
            #pragma unroll
            for (int b = 0; b < NA; b++)
                pa += sM[b * DIMV + c] * sE[(a * NA + b) * DIMV + c];
            bilp += sC[a * DIMV + c] * pa;
        }
        sRed[g * DIMV + c] = bilp;
    }
    __syncthreads();

    if (g == 0) {
        float bil = sRed[c] + sRed[DIMV + c] + sRed[2 * DIMV + c] + sRed[3 * DIMV + c];
        float wm = 0.f, mm = 0.f;
        #pragma unroll
        for (int a = 0; a < NA; a++) {
            wm += sC[a * DIMV + c];
            mm += sM[a * DIMV + c];
        }
        g_bil[m * DIMV + c] = bil;
        g_Wm[m * DIMV + c] = wm;
        g_Mm[m * DIMV + c] = mm;
    }
}

// k_out v3: 512 threads, k-split 4 ways; both weight slices hoisted to registers.
__global__ __launch_bounds__(512, 1) void k_out(
    const float* __restrict__ E_bond,
    const float* __restrict__ W0, const float* __restrict__ b0,
    const float* __restrict__ W1, const float* __restrict__ b1,
    const float* __restrict__ Wp, const float* __restrict__ bp,
    float* __restrict__ out)
{
    __shared__ float sPart[4 * DIMV];
    __shared__ float sx[DIMV];
    __shared__ float sy[DIMV];
    __shared__ float sr[4];
    const int tid = threadIdx.x;
    const int c = tid & 127;
    const int q = tid >> 7;
    const int m = blockIdx.x;

    // hoist all independent global loads to the top (one big batch)
    float w0r[32], w1r[32];
    #pragma unroll
    for (int j = 0; j < 32; j++) {
        w0r[j] = W0[(q * 32 + j) * DIMV + c];
        w1r[j] = W1[(q * 32 + j) * DIMV + c];
    }
    float sp = 0.f;
    #pragma unroll
    for (int j = 0; j < 16; j++)
        sp += g_Wm[(q * 16 + j) * DIMV + c];
    sPart[q * DIMV + c] = sp;
    float bilv = g_bil[m * DIMV + c];
    float wmv  = g_Wm[m * DIMV + c];
    float mmv  = g_Mm[m * DIMV + c];
    float e0c  = E_bond[c];
    float b0v  = b0[c];
    float b1v  = b1[c];
    __syncthreads();

    if (q == 0) {
        float S = sPart[c] + sPart[DIMV + c] + sPart[2 * DIMV + c] + sPart[3 * DIMV + c];
        sx[c] = bilv + e0c * (S - wmv) * mmv;
    }
    __syncthreads();

    // layer 0 (weights in regs, sx broadcast LDS)
    {
        const float4* x4 = (const float4*)(sx + q * 32);
        float a = 0.f;
        #pragma unroll
        for (int jv = 0; jv < 8; jv++) {
            float4 xv = x4[jv];
            a += xv.x * w0r[jv * 4 + 0];
            a += xv.y * w0r[jv * 4 + 1];
            a += xv.z * w0r[jv * 4 + 2];
            a += xv.w * w0r[jv * 4 + 3];
        }
        sPart[q * DIMV + c] = a;
    }
    __syncthreads();
    if (q == 0)
        sy[c] = fmaxf(sPart[c] + sPart[DIMV + c] + sPart[2 * DIMV + c] + sPart[3 * DIMV + c] + b0v, 0.f);
    __syncthreads();

    // layer 1
    {
        const float4* y4 = (const float4*)(sy + q * 32);
        float a = 0.f;
        #pragma unroll
        for (int jv = 0; jv < 8; jv++) {
            float4 yv = y4[jv];
            a += yv.x * w1r[jv * 4 + 0];
            a += yv.y * w1r[jv * 4 + 1];
            a += yv.z * w1r[jv * 4 + 2];
            a += yv.w * w1r[jv * 4 + 3];
        }
        sPart[q * DIMV + c] = a;
    }
    __syncthreads();

    if (q == 0) {
        float a1 = fmaxf(sPart[c] + sPart[DIMV + c] + sPart[2 * DIMV + c] + sPart[3 * DIMV + c] + b1v, 0.f);
        float r = a1 * Wp[c];
        #pragma unroll
        for (int o = 16; o > 0; o >>= 1) r += __shfl_xor_sync(0xffffffffu, r, o);
        if ((c & 31) == 0) sr[c >> 5] = r;
    }
    __syncthreads();
    if (tid == 0) out[m] = sr[0] + sr[1] + sr[2] + sr[3] + bp[0];
}

extern "C" void kernel_launch(void* const* d_in, const int* in_sizes, int n_in,
                              void* d_out, int out_size) {
    const int*   fp     = (const int*)d_in[0];
    const float* adj    = (const float*)d_in[1];
    const int*   bidx   = (const int*)d_in[2];
    const float* E_fp   = (const float*)d_in[3];
    const float* E_bond = (const float*)d_in[4];
    const float* W_fp   = (const float*)d_in[5];
    const float* b_fp   = (const float*)d_in[6];
    const float* W0     = (const float*)d_in[7];
    const float* b0     = (const float*)d_in[8];
    const float* W1     = (const float*)d_in[9];
    const float* b1     = (const float*)d_in[10];
    const float* Wp     = (const float*)d_in[11];
    const float* bp     = (const float*)d_in[12];
    float* out = (float*)d_out;

    size_t smem_bytes = SMEM_FLOATS * sizeof(float);
    cudaFuncSetAttribute(k_mol, cudaFuncAttributeMaxDynamicSharedMemorySize,
                         (int)smem_bytes);
    k_mol<<<NMOL, 512, smem_bytes>>>(fp, adj, bidx, E_fp, E_bond, W_fp, b_fp);
    k_out<<<NMOL, 512>>>(E_bond, W0, b0, W1, b1, Wp, bp, out);
}

// round 11
// speedup vs baseline: 2.8450x; 1.0131x over previous
#include <cuda_runtime.h>
#include <cstdint>

#define DIMV 128
#define NA 16
#define NMOL 64
#define NTOT 1024
#define EPSV 1e-12f

// cross-block scratch (allocation-free: __device__ globals)
__device__ float g_Wm[NMOL * DIMV];
__device__ int   g_ctr;           // monotonic grid-barrier ticket counter

// dynamic smem layout (floats)
#define OFF_E    0                    // E_bond tile: 256 x 128 = 32768
#define OFF_P    (OFF_E + 32768)      // GEMM partials 4x16x128 = 8192; phase-B scratch
#define OFF_M    (OFF_P + 8192)       // mps0 -> mps : 16x128 = 2048
#define OFF_C    (OFF_M + 2048)       // contri 16x128; later bilArr/mmArr
#define OFF_RED  (OFF_C + 2048)       // 2 x (4x128) partials = 1024
#define OFF_ADJ  (OFF_RED + 1024)     // 16x16 adjacency block
#define OFF_NORM (OFF_ADJ + 256)      // 16 inverse norms (padded)
#define OFF_IDX  (OFF_NORM + 32)      // 16 fp indices (padded)
#define OFF_IDXB (OFF_IDX + 32)       // 256 bond indices
#define SMEM_FLOATS (OFF_IDXB + 256)

extern __shared__ float smem[];

__device__ __forceinline__ void cp_async16(unsigned int saddr, const void* gptr) {
    asm volatile("cp.async.cg.shared.global [%0], [%1], 16;\n"
                 :: "r"(saddr), "l"(gptr));
}

__global__ __launch_bounds__(512, 1) void k_fused(
    const int* __restrict__ fp, const float* __restrict__ adj,
    const int* __restrict__ bidx, const float* __restrict__ E_fp,
    const float* __restrict__ E_bond, const float* __restrict__ W_fp,
    const float* __restrict__ b_fp,
    const float* __restrict__ W0, const float* __restrict__ b0,
    const float* __restrict__ W1, const float* __restrict__ b1,
    const float* __restrict__ Wp, const float* __restrict__ bp,
    float* __restrict__ out)
{
    float* sE   = smem + OFF_E;
    float* sP   = smem + OFF_P;
    float* sM   = smem + OFF_M;
    float* sC   = smem + OFF_C;
    float* sRedB = smem + OFF_RED;          // bil partials 4x128
    float* sRedW = smem + OFF_RED + 512;    // wm partials 4x128
    float* sAdj = smem + OFF_ADJ;
    float* sNorm = smem + OFF_NORM;
    int* sIdx  = (int*)(smem + OFF_IDX);
    int* sIdxB = (int*)(smem + OFF_IDXB);
    // phase-B scratch aliases sP (dead after stage 2) and sC (dead after stage 3)
    float* sPart  = sP;                 // 4x128
    float* sx     = sP + 512;           // 128
    float* sy     = sP + 640;           // 128
    float* sr     = sP + 768;           // 4
    float* bilArr = sC;                 // 128
    float* mmArr  = sC + 128;           // 128

    const int tid = threadIdx.x;
    const int m = blockIdx.x;
    const int base = m * NA;
    const int c = tid & 127;
    const int g = tid >> 7;      // 0..3
    const int r0 = 4 * g;

    // ---- stage 0: indices + adjacency + scalars + W_fp slice ----
    if (tid < NA) sIdx[tid] = fp[base + tid];
    if (tid < NA * NA) {
        int a = tid >> 4, b = tid & 15;
        sIdxB[tid] = bidx[(base + a) * NTOT + base + b];
        sAdj[tid] = adj[(base + a) * NTOT + base + b];
    }
    float bv  = b_fp[c];
    float e0c = E_bond[c];
    float b0v = b0[c];
    float b1v = b1[c];
    float wpv = Wp[c];
    float bpv = bp[0];
    float wreg[32];
    #pragma unroll
    for (int j = 0; j < 32; j++)
        wreg[j] = W_fp[(g * 32 + j) * DIMV + c];
    __syncthreads();

    // ---- stage 1: async E_bond gather (hidden) + E_fp gather ----
    {
        const float4* Eb4 = (const float4*)E_bond;
        unsigned int sE_base = (unsigned int)__cvta_generic_to_shared(sE);
        #pragma unroll
        for (int i = tid; i < NA * NA * (DIMV / 4); i += 512) {
            int row = i >> 5, cc = i & 31;
            cp_async16(sE_base + i * 16, &Eb4[sIdxB[row] * (DIMV / 4) + cc]);
        }
        asm volatile("cp.async.commit_group;\n");
    }
    {
        const float4* Ef4 = (const float4*)E_fp;
        float4* sM4 = (float4*)sM;
        int r = tid >> 5, cc = tid & 31;
        sM4[tid] = Ef4[sIdx[r] * (DIMV / 4) + cc];
    }
    __syncthreads();

    // ---- stage 2: contri GEMM partials, k-split 4 ways ----
    {
        #pragma unroll
        for (int r = 0; r < NA; r++) {
            const float4* row4 = (const float4*)(sM + r * DIMV + g * 32);
            float a = 0.f;
            #pragma unroll
            for (int jv = 0; jv < 8; jv++) {
                float4 mv = row4[jv];
                a += mv.x * wreg[jv * 4 + 0];
                a += mv.y * wreg[jv * 4 + 1];
                a += mv.z * wreg[jv * 4 + 2];
                a += mv.w * wreg[jv * 4 + 3];
            }
            sP[(g * NA + r) * DIMV + c] = a;
        }
    }
    __syncthreads();

    // reduce partials -> contri = relu(. + b)
    {
        #pragma unroll
        for (int j = 0; j < 4; j++) {
            int r = r0 + j;
            float v = bv + sP[r * DIMV + c] + sP[(NA + r) * DIMV + c]
                    + sP[(2 * NA + r) * DIMV + c] + sP[(3 * NA + r) * DIMV + c];
            sC[r * DIMV + c] = fmaxf(v, 0.f);
        }
    }
    __syncthreads();

    // ---- stage 3: mps = mps0 + adj_block @ contri (in place on sM) ----
    {
        #pragma unroll
        for (int j = 0; j < 4; j++) {
            int r = r0 + j;
            float v = sM[r * DIMV + c];
            #pragma unroll
            for (int b = 0; b < NA; b++)
                v += sAdj[r * NA + b] * sC[b * DIMV + c];
            sM[r * DIMV + c] = v;
        }
    }

    // hoist MLP weight slices now (wreg dead); loads hidden behind stages 4-5
    float w0r[32], w1r[32];
    #pragma unroll
    for (int j = 0; j < 32; j++) {
        w0r[j] = W0[(g * 32 + j) * DIMV + c];
        w1r[j] = W1[(g * 32 + j) * DIMV + c];
    }
    __syncthreads();

    // ---- stage 4: per-row L2 norms (16 warps, warp w -> row w) ----
    {
        int w = tid >> 5, l = tid & 31;
        float v0 = sM[w * DIMV + l], v1 = sM[w * DIMV + l + 32];
        float v2 = sM[w * DIMV + l + 64], v3 = sM[w * DIMV + l + 96];
        float s = v0 * v0 + v1 * v1 + v2 * v2 + v3 * v3;
        #pragma unroll
        for (int o = 16; o > 0; o >>= 1) s += __shfl_xor_sync(0xffffffffu, s, o);
        if (l == 0) sNorm[w] = 1.0f / fmaxf(sqrtf(s), EPSV);
    }
    __syncthreads();
    {
        #pragma unroll
        for (int j = 0; j < 4; j++)
            sM[(r0 + j) * DIMV + c] *= sNorm[r0 + j];
    }

    // ---- stage 5: wait E_bond; single pass -> s, pa, bil & wm partials ----
    asm volatile("cp.async.wait_group 0;\n" ::: "memory");
    __syncthreads();
    {
        float bilp = 0.f, wmp = 0.f;
        #pragma unroll
        for (int j = 0; j < 4; j++) {
            int a = r0 + j;
            float s = (float)(NTOT - NA) * e0c * e0c;
            float pa = 0.f;
            #pragma unroll
            for (int b = 0; b < NA; b++) {
                float e = sE[(a * NA + b) * DIMV + c];
                s += e * e;
                pa += sM[b * DIMV + c] * e;
            }
            float inv = 1.0f / fmaxf(sqrtf(s), EPSV);
            float wa = sM[a * DIMV + c] * inv;
            bilp += wa * pa;
            wmp += wa;
        }
        sRedB[g * DIMV + c] = bilp;
        sRedW[g * DIMV + c] = wmp;
    }
    __syncthreads();

    // ---- stage 6: final per-molecule reductions; publish Wm ----
    float wmv = 0.f;   // valid for g==0 threads (reused in phase B)
    if (g == 0) {
        float bil = sRedB[c] + sRedB[DIMV + c] + sRedB[2 * DIMV + c] + sRedB[3 * DIMV + c];
        wmv = sRedW[c] + sRedW[DIMV + c] + sRedW[2 * DIMV + c] + sRedW[3 * DIMV + c];
        float mm = 0.f;
        #pragma unroll
        for (int a = 0; a < NA; a++) mm += sM[a * DIMV + c];
        bilArr[c] = bil;
        mmArr[c]  = mm;
        g_Wm[m * DIMV + c] = wmv;
        __threadfence();
    }
    __syncthreads();

    // ---- grid barrier (ticket-based, monotonic counter, replay-safe) ----
    if (tid == 0) {
        int t = atomicAdd(&g_ctr, 1);
        int target = ((t >> 6) + 1) << 6;
        while (*(volatile int*)&g_ctr < target) __nanosleep(64);
        __threadfence();
    }
    __syncthreads();

    // ---- phase B: S, tn, 2-layer MLP, projection (q == g) ----
    {
        float sp = 0.f;
        #pragma unroll
        for (int j = 0; j < 16; j++)
            sp += g_Wm[(g * 16 + j) * DIMV + c];
        sPart[g * DIMV + c] = sp;
    }
    __syncthreads();
    if (g == 0) {
        float S = sPart[c] + sPart[DIMV + c] + sPart[2 * DIMV + c] + sPart[3 * DIMV + c];
        sx[c] = bilArr[c] + e0c * (S - wmv) * mmArr[c];
    }
    __syncthreads();

    // layer 0
    {
        const float4* x4 = (const float4*)(sx + g * 32);
        float a = 0.f;
        #pragma unroll
        for (int jv = 0; jv < 8; jv++) {
            float4 xv = x4[jv];
            a += xv.x * w0r[jv * 4 + 0];
            a += xv.y * w0r[jv * 4 + 1];
            a += xv.z * w0r[jv * 4 + 2];
            a += xv.w * w0r[jv * 4 + 3];
        }
        sPart[g * DIMV + c] = a;
    }
    __syncthreads();
    if (g == 0)
        sy[c] = fmaxf(sPart[c] + sPart[DIMV + c] + sPart[2 * DIMV + c] + sPart[3 * DIMV + c] + b0v, 0.f);
    __syncthreads();

    // layer 1
    {
        const float4* y4 = (const float4*)(sy + g * 32);
        float a = 0.f;
        #pragma unroll
        for (int jv = 0; jv < 8; jv++) {
            float4 yv = y4[jv];
            a += yv.x * w1r[jv * 4 + 0];
            a += yv.y * w1r[jv * 4 + 1];
            a += yv.z * w1r[jv * 4 + 2];
            a += yv.w * w1r[jv * 4 + 3];
        }
        sPart[g * DIMV + c] = a;
    }
    __syncthreads();

    if (g == 0) {
        float a1 = fmaxf(sPart[c] + sPart[DIMV + c] + sPart[2 * DIMV + c] + sPart[3 * DIMV + c] + b1v, 0.f);
        float r = a1 * wpv;
        #pragma unroll
        for (int o = 16; o > 0; o >>= 1) r += __shfl_xor_sync(0xffffffffu, r, o);
        if ((c & 31) == 0) sr[c >> 5] = r;
    }
    __syncthreads();
    if (tid == 0) out[m] = sr[0] + sr[1] + sr[2] + sr[3] + bpv;
}

extern "C" void kernel_launch(void* const* d_in, const int* in_sizes, int n_in,
                              void* d_out, int out_size) {
    const int*   fp     = (const int*)d_in[0];
    const float* adj    = (const float*)d_in[1];
    const int*   bidx   = (const int*)d_in[2];
    const float* E_fp   = (const float*)d_in[3];
    const float* E_bond = (const float*)d_in[4];
    const float* W_fp   = (const float*)d_in[5];
    const float* b_fp   = (const float*)d_in[6];
    const float* W0     = (const float*)d_in[7];
    const float* b0     = (const float*)d_in[8];
    const float* W1     = (const float*)d_in[9];
    const float* b1     = (const float*)d_in[10];
    const float* Wp     = (const float*)d_in[11];
    const float* bp     = (const float*)d_in[12];
    float* out = (float*)d_out;

    size_t smem_bytes = SMEM_FLOATS * sizeof(float);
    cudaFuncSetAttribute(k_fused, cudaFuncAttributeMaxDynamicSharedMemorySize,
                         (int)smem_bytes);
    k_fused<<<NMOL, 512, smem_bytes>>>(fp, adj, bidx, E_fp, E_bond, W_fp, b_fp,
                                       W0, b0, W1, b1, Wp, bp, out);
}